// round 12
// baseline (speedup 1.0000x reference)
#include <cuda_runtime.h>
#include <cstdint>
#include <cstddef>

// ---------------- device scratch (module globals: allocation-free) ----------------
#define NODES_MAX 4096
#define SMAX 64
__device__ int g_order[NODES_MAX];
__device__ int g_segStart[SMAX];
__device__ int g_segCount[SMAX];

// ---------------- grouping kernel: counting sort of nodes by species ----------------
__global__ void group_kernel(const int* __restrict__ index, int N) {
    __shared__ int cnt[SMAX];
    __shared__ int cur[SMAX];
    int tid = threadIdx.x;
    if (tid < SMAX) cnt[tid] = 0;
    __syncthreads();
    for (int i = tid; i < N; i += blockDim.x)
        atomicAdd(&cnt[index[i] & (SMAX - 1)], 1);
    __syncthreads();
    if (tid == 0) {
        int run = 0;
        for (int s = 0; s < SMAX; s++) {
            g_segStart[s] = run;
            g_segCount[s] = cnt[s];
            cur[s] = run;
            run += cnt[s];
        }
    }
    __syncthreads();
    for (int i = tid; i < N; i += blockDim.x) {
        int s = index[i] & (SMAX - 1);
        int p = atomicAdd(&cur[s], 1);
        if (p < NODES_MAX) g_order[p] = i;
    }
}

// ---------------- f32x2 helpers ----------------
typedef unsigned long long ull;
static __device__ __forceinline__ ull pk2(float v) {        // (v, v)
    ull r;
    asm("mov.b64 %0, {%1, %1};" : "=l"(r) : "r"(__float_as_uint(v)));
    return r;
}
static __device__ __forceinline__ void fma2(ull& d, ull a, ull b) {
    asm("fma.rn.f32x2 %0, %1, %2, %0;" : "+l"(d) : "l"(a), "l"(b));
}
static __device__ __forceinline__ void unpk2(ull v, float& lo, float& hi) {
    unsigned int a, b;
    asm("mov.b64 {%0, %1}, %2;" : "=r"(a), "=r"(b) : "l"(v));
    lo = __uint_as_float(a);
    hi = __uint_as_float(b);
}
static __device__ __forceinline__ float lo2(ull v) {
    unsigned int a, b;
    asm("mov.b64 {%0, %1}, %2;" : "=r"(a), "=r"(b) : "l"(v));
    return __uint_as_float(a);
}

// ---------------- layout ----------------
// Per channel c the output row base o=(n*128+c)*729 satisfies o mod 4 == c mod 4.
// Phase h(c) = (-c) mod 4: quads cover elements [h, h+4*Kq), head/tail scalar.
// uw smem stores element e of channel c at j*JSTR + (e - h) (head wrapped to end),
// so quad LDS.128 at j*JSTR + 4*q is 16B-aligned.
#define CT 8
#define JSTR 732
#define CHSTR (9 * JSTR)               // 6588
#define UW_F (CT * CHSTR)              // 52704
#define WS_OFF UW_F
#define UST_OFF (WS_OFF + 240)
#define UST_F 4752                     // staging buffer (floats), max over chunks
#define SMEM_F (UST_OFF + UST_F)       // 57696
#define SMEM_BYTES (SMEM_F * 4)        // 230,784 B

// ---------------- build helper: coalesced smem-staged u ----------------
// Per pass: copy contiguous u rows into ust (coalesced LDG.32), then compute
// items reading k-strided values from smem instead of scattered gmem.
template<int MUL, int IRR, int KOFF, int IBASE, int PASS_ITEMS>
static __device__ __forceinline__ void build_chunk_staged(
    const float* __restrict__ up, const float* __restrict__ ws,
    float* __restrict__ uw, float* __restrict__ ust, int tid)
{
    constexpr int ROWLEN = MUL * IRR;
    constexpr int ITEMS = 729 * IRR;
    constexpr int PASS_ROWS = PASS_ITEMS / IRR;
    for (int p0 = 0; p0 < ITEMS; p0 += PASS_ITEMS) {
        int row0 = p0 / IRR;
        int rows = 729 - row0;
        if (rows > PASS_ROWS) rows = PASS_ROWS;
        int F = rows * ROWLEN;
        __syncthreads();                 // previous pass's compute done
        for (int f = tid; f < F; f += 512)
            ust[f] = __ldg(up + row0 * ROWLEN + f);
        __syncthreads();
        int nit = ITEMS - p0;
        if (nit > PASS_ITEMS) nit = PASS_ITEMS;
        for (int it = tid; it < nit; it += 512) {
            int lrow = it / IRR, il = it - lrow * IRR;
            const float* ub = ust + lrow * ROWLEN + il;
            float uv[MUL];
            #pragma unroll
            for (int k = 0; k < MUL; k++) uv[k] = ub[k * IRR];
            float acc[8];
            #pragma unroll
            for (int c = 0; c < 8; c++) acc[c] = 0.f;
            #pragma unroll
            for (int k = 0; k < MUL; k++) {
                const float* wr = ws + (KOFF + k) * 8;
                #pragma unroll
                for (int c = 0; c < 8; c++) acc[c] += uv[k] * wr[c];
            }
            int grow = row0 + lrow;
            int ab = grow / 9, j = grow - ab * 9;
            int e = ab * 9 + IBASE + il;
            #pragma unroll
            for (int c = 0; c < 8; c++) {
                const int hc = (4 - (c & 3)) & 3;
                int pos = (e >= hc) ? (e - hc) : (729 - hc + e);
                uw[c * CHSTR + j * JSTR + pos] = acc[c];
            }
        }
    }
}

// ---------------- main kernel ----------------
// grid = (C/8, S), 512 threads = 16 warps: warp -> channel (wid>>1), half (wid&1).
// Mainloop = R8 core: 4 nodes/group, dup-packed x, element-pair f32x2 accs,
// aligned LDS.128 of uw, STG.128 streaming stores.
__global__ __launch_bounds__(512, 1)
void mace_kernel(const float* __restrict__ nf,
                 const float* __restrict__ u0, const float* __restrict__ u1,
                 const float* __restrict__ u2,
                 const float* __restrict__ w0, const float* __restrict__ w1,
                 const float* __restrict__ w2,
                 float* __restrict__ out, int C) {
    extern __shared__ float sm[];
    float* uw  = sm;
    float* ws  = sm + WS_OFF;
    float* ust = sm + UST_OFF;

    const int s = blockIdx.y;
    const int m = g_segCount[s];
    if (m == 0) return;             // CTA-uniform, before any barrier
    const int c0 = blockIdx.x * CT;
    const int segBase = g_segStart[s];
    const int tid = threadIdx.x;

    // ---- stage scaled species weights: ws[kglobal][c] ----
    if (tid < 240) {
        int kg = tid >> 3, c = tid & 7;
        const float* wp; int k; float scale; int mul;
        if (kg < 7)       { wp = w0; k = kg;      scale = 0.61478815f; mul = 7;  }
        else if (kg < 18) { wp = w1; k = kg - 7;  scale = 0.54910049f; mul = 11; }
        else              { wp = w2; k = kg - 18; scale = 0.53728497f; mul = 12; }
        ws[tid] = wp[((size_t)s * mul + k) * C + (c0 + c)] * scale;
    }
    __syncthreads();

    // ---- build uw via coalesced smem staging ----
    build_chunk_staged<7, 1, 0, 0, 512>(u0, ws, uw, ust, tid);
    build_chunk_staged<11, 3, 7, 1, 432>(u1, ws, uw, ust, tid);
    build_chunk_staged<12, 5, 18, 4, 360>(u2, ws, uw, ust, tid);
    __syncthreads();

    // ---- main loop (R8 core) ----
    const int lane = tid & 31;
    const int wid  = tid >> 5;          // 0..15
    const int cw   = wid >> 1;          // channel in tile
    const int q    = wid & 1;           // node-group half
    const int crow = c0 + cw;
    const float* uwC = uw + cw * CHSTR;
    const int h  = (4 - (crow & 3)) & 3;  // warp-uniform phase
    const int Kq = (729 - h) >> 2;        // full quads
    const int nL = 729 - 4 * Kq;          // leftover scalars (<=5)

    const int groups = (m + 3) >> 2;
    for (int g = q; g < groups; g += 2) {
        // gather 36 x-values (4 nodes x 9 j): v0 = el 0..31, v1 = el 32..35
        int n0 = lane / 9, j0 = lane - n0 * 9;
        int idx0 = g * 4 + n0;
        if (idx0 >= m) idx0 = m - 1;       // clamp: safe read, store masked
        int nid = g_order[segBase + idx0];
        float v0 = nf[((size_t)nid * C + crow) * 9 + j0];
        float v1 = 0.f;
        if (lane < 4) {
            int idx1 = g * 4 + 3;
            if (idx1 >= m) idx1 = m - 1;
            v1 = nf[((size_t)g_order[segBase + idx1] * C + crow) * 9 + (5 + lane)];
        }

        unsigned o[4];
        bool valid[4];
        #pragma unroll
        for (int nd = 0; nd < 4; nd++) {
            int n4 = __shfl_sync(0xffffffffu, nid, nd * 9);
            valid[nd] = (g * 4 + nd) < m;
            o[nd] = (unsigned)(n4 * C + crow) * 729u;
        }

        // dup-packed x: xd[nd][j] = (x, x)
        ull xd[4][9];
        #pragma unroll
        for (int nd = 0; nd < 4; nd++) {
            #pragma unroll
            for (int j = 0; j < 9; j++) {
                int el = nd * 9 + j;
                float xv = (el < 32) ? __shfl_sync(0xffffffffu, v0, el)
                                     : __shfl_sync(0xffffffffu, v1, el - 32);
                xd[nd][j] = pk2(xv);
            }
        }

        // body: quads qi = it*32 + lane, elements E = h + 4*qi
        #pragma unroll 1
        for (int it = 0; it < 6; it++) {
            int qi = it * 32 + lane;
            bool act = qi < Kq;
            int qc = act ? qi : 0;
            int soff = 4 * qc;
            ull aA[4] = {0ull, 0ull, 0ull, 0ull};   // (E, E+1)
            ull aB[4] = {0ull, 0ull, 0ull, 0ull};   // (E+2, E+3)
            #pragma unroll
            for (int j = 0; j < 9; j++) {
                ulonglong2 uv = *reinterpret_cast<const ulonglong2*>(uwC + j * JSTR + soff);
                fma2(aA[0], uv.x, xd[0][j]);  fma2(aB[0], uv.y, xd[0][j]);
                fma2(aA[1], uv.x, xd[1][j]);  fma2(aB[1], uv.y, xd[1][j]);
                fma2(aA[2], uv.x, xd[2][j]);  fma2(aB[2], uv.y, xd[2][j]);
                fma2(aA[3], uv.x, xd[3][j]);  fma2(aB[3], uv.y, xd[3][j]);
            }
            int E = h + 4 * qc;
            #pragma unroll
            for (int nd = 0; nd < 4; nd++) {
                float4 f4;
                unpk2(aA[nd], f4.x, f4.y);
                unpk2(aB[nd], f4.z, f4.w);
                if (act && valid[nd])
                    __stcs(reinterpret_cast<float4*>(out + o[nd] + E), f4);
            }
        }

        // leftovers: head elements [0,h) and tail [h+4Kq, 729): nL lanes
        if (lane < nL) {
            int e   = (lane < h) ? lane : (4 * Kq + lane);
            int pos = (lane < h) ? (729 - h + lane) : (4 * Kq + lane - h);
            float b0 = 0.f, b1 = 0.f, b2 = 0.f, b3 = 0.f;
            #pragma unroll
            for (int j = 0; j < 9; j++) {
                float uvv = uwC[j * JSTR + pos];
                b0 += uvv * lo2(xd[0][j]);
                b1 += uvv * lo2(xd[1][j]);
                b2 += uvv * lo2(xd[2][j]);
                b3 += uvv * lo2(xd[3][j]);
            }
            if (valid[0]) __stcs(out + o[0] + e, b0);
            if (valid[1]) __stcs(out + o[1] + e, b1);
            if (valid[2]) __stcs(out + o[2] + e, b2);
            if (valid[3]) __stcs(out + o[3] + e, b3);
        }
    }
}

// ---------------- launch ----------------
extern "C" void kernel_launch(void* const* d_in, const int* in_sizes, int n_in,
                              void* d_out, int out_size) {
    const float *nf = nullptr, *u0 = nullptr, *u1 = nullptr, *u2 = nullptr;
    const float *w0 = nullptr, *w1 = nullptr, *w2 = nullptr;
    const int* index = nullptr;
    int N = 0, nf_sz = 0, w0_sz = 0;
    for (int i = 0; i < n_in; i++) {
        int sz = in_sizes[i];
        switch (sz) {
            case 5103:    u0 = (const float*)d_in[i]; break;
            case 24057:   u1 = (const float*)d_in[i]; break;
            case 43740:   u2 = (const float*)d_in[i]; break;
            case 44800:   w0 = (const float*)d_in[i]; w0_sz = sz; break;
            case 70400:   w1 = (const float*)d_in[i]; break;
            case 76800:   w2 = (const float*)d_in[i]; break;
            case 2048:    index = (const int*)d_in[i]; N = sz; break;
            case 2359296: nf = (const float*)d_in[i]; nf_sz = sz; break;
            default: break;
        }
    }
    if (!nf || !index || !u0 || !u1 || !u2 || !w0 || !w1 || !w2) return;

    const int C = nf_sz / (N * 9);        // 128
    const int S = w0_sz / (7 * C);        // 50

    group_kernel<<<1, 256>>>(index, N);

    cudaFuncSetAttribute(mace_kernel,
                         cudaFuncAttributeMaxDynamicSharedMemorySize, SMEM_BYTES);
    dim3 grid(C / CT, S);
    mace_kernel<<<grid, 512, SMEM_BYTES>>>(nf, u0, u1, u2, w0, w1, w2,
                                           (float*)d_out, C);
}

// round 13
// speedup vs baseline: 1.3567x; 1.3567x over previous
#include <cuda_runtime.h>
#include <cstdint>
#include <cstddef>

// ---------------- device scratch (module globals: allocation-free) ----------------
#define NODES_MAX 4096
#define SMAX 64
__device__ int g_order[NODES_MAX];
__device__ int g_segStart[SMAX];
__device__ int g_segCount[SMAX];
// k-major transposed u basis tensors (constant per launch, built by prep_kernel)
__device__ float g_u0t[7 * 729];        // [k][row]        (IRR=1)
__device__ float g_u1t[11 * 729 * 3];   // [k][row*3+il]   (IRR=3)
__device__ float g_u2t[12 * 729 * 5];   // [k][row*5+il]   (IRR=5)

// ---------------- grouping kernel: counting sort of nodes by species ----------------
__global__ void group_kernel(const int* __restrict__ index, int N) {
    __shared__ int cnt[SMAX];
    __shared__ int cur[SMAX];
    int tid = threadIdx.x;
    if (tid < SMAX) cnt[tid] = 0;
    __syncthreads();
    for (int i = tid; i < N; i += blockDim.x)
        atomicAdd(&cnt[index[i] & (SMAX - 1)], 1);
    __syncthreads();
    if (tid == 0) {
        int run = 0;
        for (int s = 0; s < SMAX; s++) {
            g_segStart[s] = run;
            g_segCount[s] = cnt[s];
            cur[s] = run;
            run += cnt[s];
        }
    }
    __syncthreads();
    for (int i = tid; i < N; i += blockDim.x) {
        int s = index[i] & (SMAX - 1);
        int p = atomicAdd(&cur[s], 1);
        if (p < NODES_MAX) g_order[p] = i;
    }
}

// ---------------- prep kernel: transpose u to k-major (once per launch) ----------------
__global__ void prep_kernel(const float* __restrict__ u0,
                            const float* __restrict__ u1,
                            const float* __restrict__ u2) {
    int t = blockIdx.x * blockDim.x + threadIdx.x;
    int T = gridDim.x * blockDim.x;
    for (int f = t; f < 729 * 7; f += T) {          // u0: row-major [row][k]
        int row = f / 7, k = f - row * 7;
        g_u0t[k * 729 + row] = u0[f];
    }
    for (int f = t; f < 729 * 33; f += T) {         // u1: [row][k][il]
        int row = f / 33, r2 = f - row * 33;
        int k = r2 / 3, il = r2 - k * 3;
        g_u1t[k * 2187 + row * 3 + il] = u1[f];
    }
    for (int f = t; f < 729 * 60; f += T) {         // u2: [row][k][il]
        int row = f / 60, r2 = f - row * 60;
        int k = r2 / 5, il = r2 - k * 5;
        g_u2t[k * 3645 + row * 5 + il] = u2[f];
    }
}

// ---------------- f32x2 helpers ----------------
typedef unsigned long long ull;
static __device__ __forceinline__ ull pk2(float v) {        // (v, v)
    ull r;
    asm("mov.b64 %0, {%1, %1};" : "=l"(r) : "r"(__float_as_uint(v)));
    return r;
}
static __device__ __forceinline__ void fma2(ull& d, ull a, ull b) {
    asm("fma.rn.f32x2 %0, %1, %2, %0;" : "+l"(d) : "l"(a), "l"(b));
}
static __device__ __forceinline__ void unpk2(ull v, float& lo, float& hi) {
    unsigned int a, b;
    asm("mov.b64 {%0, %1}, %2;" : "=r"(a), "=r"(b) : "l"(v));
    lo = __uint_as_float(a);
    hi = __uint_as_float(b);
}
static __device__ __forceinline__ float lo2(ull v) {
    unsigned int a, b;
    asm("mov.b64 {%0, %1}, %2;" : "=r"(a), "=r"(b) : "l"(v));
    return __uint_as_float(a);
}

// ---------------- layout ----------------
// Per channel c the output row base o=(n*128+c)*729 satisfies o mod 4 == c mod 4.
// Phase h(c) = (-c) mod 4: quads cover elements [h, h+4*Kq), head/tail scalar.
// uw smem stores element e of channel c at j*JSTR + (e - h) (head wrapped to end),
// so quad LDS.128 at j*JSTR + 4*q is 16B-aligned.
#define CT 8
#define JSTR 732
#define CHSTR (9 * JSTR)               // 6588
#define UW_F (CT * CHSTR)              // 52704
#define WS_OFF UW_F
#define SMEM_BYTES ((UW_F + 240) * 4)  // 211,776 B

// ---------------- build helper: k-major coalesced u loads ----------------
// u_t layout: [k][729*IRR]; idx = row*IRR + il is thread-linear -> every
// warp-LDG covers 32 consecutive floats = 1 L1 wavefront.
template<int MUL, int IRR, int KOFF, int IBASE>
static __device__ __forceinline__ void build_chunk(const float* __restrict__ ut,
                                                   const float* __restrict__ ws,
                                                   float* __restrict__ uw, int tid) {
    constexpr int ITEMS = 729 * IRR;
    for (int idx = tid; idx < ITEMS; idx += 512) {
        float uv[MUL];
        #pragma unroll
        for (int k = 0; k < MUL; k++) uv[k] = __ldg(ut + k * ITEMS + idx);
        float acc[8];
        #pragma unroll
        for (int c = 0; c < 8; c++) acc[c] = 0.f;
        #pragma unroll
        for (int k = 0; k < MUL; k++) {
            const float* wr = ws + (KOFF + k) * 8;
            #pragma unroll
            for (int c = 0; c < 8; c++) acc[c] += uv[k] * wr[c];
        }
        int row = idx / IRR;
        int il  = idx - row * IRR;
        int ab  = row / 9;
        int j   = row - ab * 9;
        int e   = ab * 9 + IBASE + il;
        #pragma unroll
        for (int c = 0; c < 8; c++) {
            const int hc = (4 - (c & 3)) & 3;
            int pos = (e >= hc) ? (e - hc) : (729 - hc + e);
            uw[c * CHSTR + j * JSTR + pos] = acc[c];
        }
    }
}

// ---------------- main kernel ----------------
// grid = (C/8, S), 512 threads = 16 warps: warp -> channel (wid>>1), half (wid&1).
// Mainloop = R8 core: 4 nodes/group, dup-packed x, element-pair f32x2 accs,
// aligned LDS.128 of uw, STG.128 streaming stores.
__global__ __launch_bounds__(512, 1)
void mace_kernel(const float* __restrict__ nf,
                 const float* __restrict__ w0, const float* __restrict__ w1,
                 const float* __restrict__ w2,
                 float* __restrict__ out, int C) {
    extern __shared__ float sm[];
    float* uw = sm;
    float* ws = sm + WS_OFF;

    const int s = blockIdx.y;
    const int m = g_segCount[s];
    if (m == 0) return;             // CTA-uniform, before any barrier
    const int c0 = blockIdx.x * CT;
    const int segBase = g_segStart[s];
    const int tid = threadIdx.x;

    // ---- stage scaled species weights: ws[kglobal][c] ----
    if (tid < 240) {
        int kg = tid >> 3, c = tid & 7;
        const float* wp; int k; float scale; int mul;
        if (kg < 7)       { wp = w0; k = kg;      scale = 0.61478815f; mul = 7;  }
        else if (kg < 18) { wp = w1; k = kg - 7;  scale = 0.54910049f; mul = 11; }
        else              { wp = w2; k = kg - 18; scale = 0.53728497f; mul = 12; }
        ws[tid] = wp[((size_t)s * mul + k) * C + (c0 + c)] * scale;
    }
    __syncthreads();

    // ---- build uw from k-major u_t (coalesced, batched LDG) ----
    build_chunk<7, 1, 0, 0>(g_u0t, ws, uw, tid);
    build_chunk<11, 3, 7, 1>(g_u1t, ws, uw, tid);
    build_chunk<12, 5, 18, 4>(g_u2t, ws, uw, tid);
    __syncthreads();

    // ---- main loop (R8 core) ----
    const int lane = tid & 31;
    const int wid  = tid >> 5;          // 0..15
    const int cw   = wid >> 1;          // channel in tile
    const int q    = wid & 1;           // node-group half
    const int crow = c0 + cw;
    const float* uwC = uw + cw * CHSTR;
    const int h  = (4 - (crow & 3)) & 3;  // warp-uniform phase
    const int Kq = (729 - h) >> 2;        // full quads
    const int nL = 729 - 4 * Kq;          // leftover scalars (<=5)

    const int groups = (m + 3) >> 2;
    for (int g = q; g < groups; g += 2) {
        // gather 36 x-values (4 nodes x 9 j): v0 = el 0..31, v1 = el 32..35
        int n0 = lane / 9, j0 = lane - n0 * 9;
        int idx0 = g * 4 + n0;
        if (idx0 >= m) idx0 = m - 1;       // clamp: safe read, store masked
        int nid = g_order[segBase + idx0];
        float v0 = nf[((size_t)nid * C + crow) * 9 + j0];
        float v1 = 0.f;
        if (lane < 4) {
            int idx1 = g * 4 + 3;
            if (idx1 >= m) idx1 = m - 1;
            v1 = nf[((size_t)g_order[segBase + idx1] * C + crow) * 9 + (5 + lane)];
        }

        unsigned o[4];
        bool valid[4];
        #pragma unroll
        for (int nd = 0; nd < 4; nd++) {
            int n4 = __shfl_sync(0xffffffffu, nid, nd * 9);
            valid[nd] = (g * 4 + nd) < m;
            o[nd] = (unsigned)(n4 * C + crow) * 729u;
        }

        // dup-packed x: xd[nd][j] = (x, x)
        ull xd[4][9];
        #pragma unroll
        for (int nd = 0; nd < 4; nd++) {
            #pragma unroll
            for (int j = 0; j < 9; j++) {
                int el = nd * 9 + j;
                float xv = (el < 32) ? __shfl_sync(0xffffffffu, v0, el)
                                     : __shfl_sync(0xffffffffu, v1, el - 32);
                xd[nd][j] = pk2(xv);
            }
        }

        // body: quads qi = it*32 + lane, elements E = h + 4*qi
        #pragma unroll 1
        for (int it = 0; it < 6; it++) {
            int qi = it * 32 + lane;
            bool act = qi < Kq;
            int qc = act ? qi : 0;
            int soff = 4 * qc;
            ull aA[4] = {0ull, 0ull, 0ull, 0ull};   // (E, E+1)
            ull aB[4] = {0ull, 0ull, 0ull, 0ull};   // (E+2, E+3)
            #pragma unroll
            for (int j = 0; j < 9; j++) {
                ulonglong2 uv = *reinterpret_cast<const ulonglong2*>(uwC + j * JSTR + soff);
                fma2(aA[0], uv.x, xd[0][j]);  fma2(aB[0], uv.y, xd[0][j]);
                fma2(aA[1], uv.x, xd[1][j]);  fma2(aB[1], uv.y, xd[1][j]);
                fma2(aA[2], uv.x, xd[2][j]);  fma2(aB[2], uv.y, xd[2][j]);
                fma2(aA[3], uv.x, xd[3][j]);  fma2(aB[3], uv.y, xd[3][j]);
            }
            int E = h + 4 * qc;
            #pragma unroll
            for (int nd = 0; nd < 4; nd++) {
                float4 f4;
                unpk2(aA[nd], f4.x, f4.y);
                unpk2(aB[nd], f4.z, f4.w);
                if (act && valid[nd])
                    __stcs(reinterpret_cast<float4*>(out + o[nd] + E), f4);
            }
        }

        // leftovers: head elements [0,h) and tail [h+4Kq, 729): nL lanes
        if (lane < nL) {
            int e   = (lane < h) ? lane : (4 * Kq + lane);
            int pos = (lane < h) ? (729 - h + lane) : (4 * Kq + lane - h);
            float b0 = 0.f, b1 = 0.f, b2 = 0.f, b3 = 0.f;
            #pragma unroll
            for (int j = 0; j < 9; j++) {
                float uvv = uwC[j * JSTR + pos];
                b0 += uvv * lo2(xd[0][j]);
                b1 += uvv * lo2(xd[1][j]);
                b2 += uvv * lo2(xd[2][j]);
                b3 += uvv * lo2(xd[3][j]);
            }
            if (valid[0]) __stcs(out + o[0] + e, b0);
            if (valid[1]) __stcs(out + o[1] + e, b1);
            if (valid[2]) __stcs(out + o[2] + e, b2);
            if (valid[3]) __stcs(out + o[3] + e, b3);
        }
    }
}

// ---------------- launch ----------------
extern "C" void kernel_launch(void* const* d_in, const int* in_sizes, int n_in,
                              void* d_out, int out_size) {
    const float *nf = nullptr, *u0 = nullptr, *u1 = nullptr, *u2 = nullptr;
    const float *w0 = nullptr, *w1 = nullptr, *w2 = nullptr;
    const int* index = nullptr;
    int N = 0, nf_sz = 0, w0_sz = 0;
    for (int i = 0; i < n_in; i++) {
        int sz = in_sizes[i];
        switch (sz) {
            case 5103:    u0 = (const float*)d_in[i]; break;
            case 24057:   u1 = (const float*)d_in[i]; break;
            case 43740:   u2 = (const float*)d_in[i]; break;
            case 44800:   w0 = (const float*)d_in[i]; w0_sz = sz; break;
            case 70400:   w1 = (const float*)d_in[i]; break;
            case 76800:   w2 = (const float*)d_in[i]; break;
            case 2048:    index = (const int*)d_in[i]; N = sz; break;
            case 2359296: nf = (const float*)d_in[i]; nf_sz = sz; break;
            default: break;
        }
    }
    if (!nf || !index || !u0 || !u1 || !u2 || !w0 || !w1 || !w2) return;

    const int C = nf_sz / (N * 9);        // 128
    const int S = w0_sz / (7 * C);        // 50

    group_kernel<<<1, 256>>>(index, N);
    prep_kernel<<<64, 256>>>(u0, u1, u2);

    cudaFuncSetAttribute(mace_kernel,
                         cudaFuncAttributeMaxDynamicSharedMemorySize, SMEM_BYTES);
    dim3 grid(C / CT, S);
    mace_kernel<<<grid, 512, SMEM_BYTES>>>(nf, w0, w1, w2, (float*)d_out, C);
}

// round 14
// speedup vs baseline: 1.3725x; 1.0117x over previous
#include <cuda_runtime.h>
#include <cstdint>
#include <cstddef>

// ---------------- device scratch (module globals: allocation-free) ----------------
#define NODES_MAX 4096
#define SMAX 64
__device__ int g_order[NODES_MAX];
__device__ int g_segStart[SMAX];
__device__ int g_segCount[SMAX];
// k-major transposed u basis tensors (constant per launch, built by setup_kernel)
__device__ float g_u0t[7 * 729];        // [k][row]        (IRR=1)
__device__ float g_u1t[11 * 729 * 3];   // [k][row*3+il]   (IRR=3)
__device__ float g_u2t[12 * 729 * 5];   // [k][row*5+il]   (IRR=5)

// ---------------- setup kernel: block 0 = counting sort; blocks 1.. = u transpose ----
__global__ void setup_kernel(const int* __restrict__ index, int N,
                             const float* __restrict__ u0,
                             const float* __restrict__ u1,
                             const float* __restrict__ u2) {
    if (blockIdx.x == 0) {
        // counting sort of nodes by species (1024 threads)
        __shared__ int cnt[SMAX];
        __shared__ int cur[SMAX];
        int tid = threadIdx.x;
        if (tid < SMAX) cnt[tid] = 0;
        __syncthreads();
        for (int i = tid; i < N; i += blockDim.x)
            atomicAdd(&cnt[index[i] & (SMAX - 1)], 1);
        __syncthreads();
        if (tid < 64) {
            // warp-pair inclusive scan over 64 counts via two warps + fixup
            // simple: thread 0..63 serial-free scan using shfl within 2 warps
        }
        if (tid == 0) {
            int run = 0;
            #pragma unroll
            for (int s = 0; s < SMAX; s++) {
                g_segStart[s] = run;
                g_segCount[s] = cnt[s];
                cur[s] = run;
                run += cnt[s];
            }
        }
        __syncthreads();
        for (int i = tid; i < N; i += blockDim.x) {
            int s = index[i] & (SMAX - 1);
            int p = atomicAdd(&cur[s], 1);
            if (p < NODES_MAX) g_order[p] = i;
        }
    } else {
        // u transpose to k-major, spread over blocks 1..gridDim-1
        int t = (blockIdx.x - 1) * blockDim.x + threadIdx.x;
        int T = (gridDim.x - 1) * blockDim.x;
        for (int f = t; f < 729 * 7; f += T) {          // u0: [row][k]
            int row = f / 7, k = f - row * 7;
            g_u0t[k * 729 + row] = u0[f];
        }
        for (int f = t; f < 729 * 33; f += T) {         // u1: [row][k][il]
            int row = f / 33, r2 = f - row * 33;
            int k = r2 / 3, il = r2 - k * 3;
            g_u1t[k * 2187 + row * 3 + il] = u1[f];
        }
        for (int f = t; f < 729 * 60; f += T) {         // u2: [row][k][il]
            int row = f / 60, r2 = f - row * 60;
            int k = r2 / 5, il = r2 - k * 5;
            g_u2t[k * 3645 + row * 5 + il] = u2[f];
        }
    }
}

// ---------------- f32x2 helpers ----------------
typedef unsigned long long ull;
static __device__ __forceinline__ ull pk2(float v) {        // (v, v)
    ull r;
    asm("mov.b64 %0, {%1, %1};" : "=l"(r) : "r"(__float_as_uint(v)));
    return r;
}
static __device__ __forceinline__ void fma2(ull& d, ull a, ull b) {
    asm("fma.rn.f32x2 %0, %1, %2, %0;" : "+l"(d) : "l"(a), "l"(b));
}
static __device__ __forceinline__ void unpk2(ull v, float& lo, float& hi) {
    unsigned int a, b;
    asm("mov.b64 {%0, %1}, %2;" : "=r"(a), "=r"(b) : "l"(v));
    lo = __uint_as_float(a);
    hi = __uint_as_float(b);
}
static __device__ __forceinline__ float lo2(ull v) {
    unsigned int a, b;
    asm("mov.b64 {%0, %1}, %2;" : "=r"(a), "=r"(b) : "l"(v));
    return __uint_as_float(a);
}

// ---------------- layout ----------------
// Per channel c the output row base o=(n*128+c)*729 satisfies o mod 4 == c mod 4.
// Phase h(c) = (-c) mod 4: quads cover elements [h, h+4*Kq), head/tail scalar.
// uw smem stores element e of channel c at j*JSTR + (e - h) (head wrapped to end),
// so quad LDS.128 at j*JSTR + 4*q is 16B-aligned.
#define CT 8
#define JSTR 732
#define CHSTR (9 * JSTR)               // 6588
#define UW_F (CT * CHSTR)              // 52704
#define WS_OFF UW_F
#define SMEM_BYTES ((UW_F + 240) * 4)  // 211,776 B

// ---------------- build helper: k-major coalesced u loads ----------------
template<int MUL, int IRR, int KOFF, int IBASE>
static __device__ __forceinline__ void build_chunk(const float* __restrict__ ut,
                                                   const float* __restrict__ ws,
                                                   float* __restrict__ uw, int tid) {
    constexpr int ITEMS = 729 * IRR;
    for (int idx = tid; idx < ITEMS; idx += 512) {
        float uv[MUL];
        #pragma unroll
        for (int k = 0; k < MUL; k++) uv[k] = __ldg(ut + k * ITEMS + idx);
        float acc[8];
        #pragma unroll
        for (int c = 0; c < 8; c++) acc[c] = 0.f;
        #pragma unroll
        for (int k = 0; k < MUL; k++) {
            const float* wr = ws + (KOFF + k) * 8;
            #pragma unroll
            for (int c = 0; c < 8; c++) acc[c] += uv[k] * wr[c];
        }
        int row = idx / IRR;
        int il  = idx - row * IRR;
        int ab  = row / 9;
        int j   = row - ab * 9;
        int e   = ab * 9 + IBASE + il;
        #pragma unroll
        for (int c = 0; c < 8; c++) {
            const int hc = (4 - (c & 3)) & 3;
            int pos = (e >= hc) ? (e - hc) : (729 - hc + e);
            uw[c * CHSTR + j * JSTR + pos] = acc[c];
        }
    }
}

// ---------------- main kernel ----------------
// grid = (C/8, S), 512 threads = 16 warps: warp -> channel (wid>>1), half (wid&1).
// Mainloop = R8 core: 4 nodes/group, dup-packed x, element-pair f32x2 accs,
// aligned LDS.128 of uw, STG.128 streaming stores.
__global__ __launch_bounds__(512, 1)
void mace_kernel(const float* __restrict__ nf,
                 const float* __restrict__ w0, const float* __restrict__ w1,
                 const float* __restrict__ w2,
                 float* __restrict__ out, int C) {
    extern __shared__ float sm[];
    float* uw = sm;
    float* ws = sm + WS_OFF;

    const int s = blockIdx.y;
    const int m = g_segCount[s];
    if (m == 0) return;             // CTA-uniform, before any barrier
    const int c0 = blockIdx.x * CT;
    const int segBase = g_segStart[s];
    const int tid = threadIdx.x;

    // ---- stage scaled species weights: ws[kglobal][c] ----
    if (tid < 240) {
        int kg = tid >> 3, c = tid & 7;
        const float* wp; int k; float scale; int mul;
        if (kg < 7)       { wp = w0; k = kg;      scale = 0.61478815f; mul = 7;  }
        else if (kg < 18) { wp = w1; k = kg - 7;  scale = 0.54910049f; mul = 11; }
        else              { wp = w2; k = kg - 18; scale = 0.53728497f; mul = 12; }
        ws[tid] = wp[((size_t)s * mul + k) * C + (c0 + c)] * scale;
    }
    __syncthreads();

    // ---- build uw from k-major u_t (coalesced, batched LDG) ----
    build_chunk<7, 1, 0, 0>(g_u0t, ws, uw, tid);
    build_chunk<11, 3, 7, 1>(g_u1t, ws, uw, tid);
    build_chunk<12, 5, 18, 4>(g_u2t, ws, uw, tid);
    __syncthreads();

    // ---- main loop (R8 core) ----
    const int lane = tid & 31;
    const int wid  = tid >> 5;          // 0..15
    const int cw   = wid >> 1;          // channel in tile
    const int q    = wid & 1;           // node-group half
    const int crow = c0 + cw;
    const float* uwC = uw + cw * CHSTR;
    const int h  = (4 - (crow & 3)) & 3;  // warp-uniform phase
    const int Kq = (729 - h) >> 2;        // full quads
    const int nL = 729 - 4 * Kq;          // leftover scalars (<=5)

    const int groups = (m + 3) >> 2;
    for (int g = q; g < groups; g += 2) {
        // gather 36 x-values (4 nodes x 9 j): v0 = el 0..31, v1 = el 32..35
        int n0 = lane / 9, j0 = lane - n0 * 9;
        int idx0 = g * 4 + n0;
        if (idx0 >= m) idx0 = m - 1;       // clamp: safe read, store masked
        int nid = g_order[segBase + idx0];
        float v0 = nf[((size_t)nid * C + crow) * 9 + j0];
        float v1 = 0.f;
        if (lane < 4) {
            int idx1 = g * 4 + 3;
            if (idx1 >= m) idx1 = m - 1;
            v1 = nf[((size_t)g_order[segBase + idx1] * C + crow) * 9 + (5 + lane)];
        }

        unsigned o[4];
        bool valid[4];
        #pragma unroll
        for (int nd = 0; nd < 4; nd++) {
            int n4 = __shfl_sync(0xffffffffu, nid, nd * 9);
            valid[nd] = (g * 4 + nd) < m;
            o[nd] = (unsigned)(n4 * C + crow) * 729u;
        }

        // dup-packed x: xd[nd][j] = (x, x)
        ull xd[4][9];
        #pragma unroll
        for (int nd = 0; nd < 4; nd++) {
            #pragma unroll
            for (int j = 0; j < 9; j++) {
                int el = nd * 9 + j;
                float xv = (el < 32) ? __shfl_sync(0xffffffffu, v0, el)
                                     : __shfl_sync(0xffffffffu, v1, el - 32);
                xd[nd][j] = pk2(xv);
            }
        }

        // body: quads qi = it*32 + lane, elements E = h + 4*qi
        #pragma unroll 1
        for (int it = 0; it < 6; it++) {
            int qi = it * 32 + lane;
            bool act = qi < Kq;
            int qc = act ? qi : 0;
            int soff = 4 * qc;
            ull aA[4] = {0ull, 0ull, 0ull, 0ull};   // (E, E+1)
            ull aB[4] = {0ull, 0ull, 0ull, 0ull};   // (E+2, E+3)
            #pragma unroll
            for (int j = 0; j < 9; j++) {
                ulonglong2 uv = *reinterpret_cast<const ulonglong2*>(uwC + j * JSTR + soff);
                fma2(aA[0], uv.x, xd[0][j]);  fma2(aB[0], uv.y, xd[0][j]);
                fma2(aA[1], uv.x, xd[1][j]);  fma2(aB[1], uv.y, xd[1][j]);
                fma2(aA[2], uv.x, xd[2][j]);  fma2(aB[2], uv.y, xd[2][j]);
                fma2(aA[3], uv.x, xd[3][j]);  fma2(aB[3], uv.y, xd[3][j]);
            }
            int E = h + 4 * qc;
            #pragma unroll
            for (int nd = 0; nd < 4; nd++) {
                float4 f4;
                unpk2(aA[nd], f4.x, f4.y);
                unpk2(aB[nd], f4.z, f4.w);
                if (act && valid[nd])
                    __stcs(reinterpret_cast<float4*>(out + o[nd] + E), f4);
            }
        }

        // leftovers: head elements [0,h) and tail [h+4Kq, 729): nL lanes
        if (lane < nL) {
            int e   = (lane < h) ? lane : (4 * Kq + lane);
            int pos = (lane < h) ? (729 - h + lane) : (4 * Kq + lane - h);
            float b0 = 0.f, b1 = 0.f, b2 = 0.f, b3 = 0.f;
            #pragma unroll
            for (int j = 0; j < 9; j++) {
                float uvv = uwC[j * JSTR + pos];
                b0 += uvv * lo2(xd[0][j]);
                b1 += uvv * lo2(xd[1][j]);
                b2 += uvv * lo2(xd[2][j]);
                b3 += uvv * lo2(xd[3][j]);
            }
            if (valid[0]) __stcs(out + o[0] + e, b0);
            if (valid[1]) __stcs(out + o[1] + e, b1);
            if (valid[2]) __stcs(out + o[2] + e, b2);
            if (valid[3]) __stcs(out + o[3] + e, b3);
        }
    }
}

// ---------------- launch ----------------
extern "C" void kernel_launch(void* const* d_in, const int* in_sizes, int n_in,
                              void* d_out, int out_size) {
    const float *nf = nullptr, *u0 = nullptr, *u1 = nullptr, *u2 = nullptr;
    const float *w0 = nullptr, *w1 = nullptr, *w2 = nullptr;
    const int* index = nullptr;
    int N = 0, nf_sz = 0, w0_sz = 0;
    for (int i = 0; i < n_in; i++) {
        int sz = in_sizes[i];
        switch (sz) {
            case 5103:    u0 = (const float*)d_in[i]; break;
            case 24057:   u1 = (const float*)d_in[i]; break;
            case 43740:   u2 = (const float*)d_in[i]; break;
            case 44800:   w0 = (const float*)d_in[i]; w0_sz = sz; break;
            case 70400:   w1 = (const float*)d_in[i]; break;
            case 76800:   w2 = (const float*)d_in[i]; break;
            case 2048:    index = (const int*)d_in[i]; N = sz; break;
            case 2359296: nf = (const float*)d_in[i]; nf_sz = sz; break;
            default: break;
        }
    }
    if (!nf || !index || !u0 || !u1 || !u2 || !w0 || !w1 || !w2) return;

    const int C = nf_sz / (N * 9);        // 128
    const int S = w0_sz / (7 * C);        // 50

    setup_kernel<<<17, 1024>>>(index, N, u0, u1, u2);

    cudaFuncSetAttribute(mace_kernel,
                         cudaFuncAttributeMaxDynamicSharedMemorySize, SMEM_BYTES);
    dim3 grid(C / CT, S);
    mace_kernel<<<grid, 512, SMEM_BYTES>>>(nf, w0, w1, w2, (float*)d_out, C);
}

// round 15
// speedup vs baseline: 1.3871x; 1.0106x over previous
#include <cuda_runtime.h>
#include <cstdint>
#include <cstddef>

// ---------------- device scratch (module globals: allocation-free) ----------------
#define NODES_MAX 4096
#define SMAX 64
__device__ int g_order[NODES_MAX];
__device__ int g_segStart[SMAX];
__device__ int g_segCount[SMAX];
// k-major transposed u basis tensors (constant per launch, built by setup_kernel)
__device__ float g_u0t[7 * 729];        // [k][row]        (IRR=1)
__device__ float g_u1t[11 * 729 * 3];   // [k][row*3+il]   (IRR=3)
__device__ float g_u2t[12 * 729 * 5];   // [k][row*5+il]   (IRR=5)

// ---------------- setup kernel: block 0 = counting sort; blocks 1.. = u transpose ----
__global__ void setup_kernel(const int* __restrict__ index, int N,
                             const float* __restrict__ u0,
                             const float* __restrict__ u1,
                             const float* __restrict__ u2) {
    if (blockIdx.x == 0) {
        __shared__ int cnt[SMAX];
        __shared__ int cur[SMAX];
        int tid = threadIdx.x;
        if (tid < SMAX) cnt[tid] = 0;
        __syncthreads();
        for (int i = tid; i < N; i += blockDim.x)
            atomicAdd(&cnt[index[i] & (SMAX - 1)], 1);
        __syncthreads();
        if (tid == 0) {
            int run = 0;
            #pragma unroll
            for (int s = 0; s < SMAX; s++) {
                g_segStart[s] = run;
                g_segCount[s] = cnt[s];
                cur[s] = run;
                run += cnt[s];
            }
        }
        __syncthreads();
        for (int i = tid; i < N; i += blockDim.x) {
            int s = index[i] & (SMAX - 1);
            int p = atomicAdd(&cur[s], 1);
            if (p < NODES_MAX) g_order[p] = i;
        }
    } else {
        int t = (blockIdx.x - 1) * blockDim.x + threadIdx.x;
        int T = (gridDim.x - 1) * blockDim.x;
        for (int f = t; f < 729 * 7; f += T) {          // u0: [row][k]
            int row = f / 7, k = f - row * 7;
            g_u0t[k * 729 + row] = u0[f];
        }
        for (int f = t; f < 729 * 33; f += T) {         // u1: [row][k][il]
            int row = f / 33, r2 = f - row * 33;
            int k = r2 / 3, il = r2 - k * 3;
            g_u1t[k * 2187 + row * 3 + il] = u1[f];
        }
        for (int f = t; f < 729 * 60; f += T) {         // u2: [row][k][il]
            int row = f / 60, r2 = f - row * 60;
            int k = r2 / 5, il = r2 - k * 5;
            g_u2t[k * 3645 + row * 5 + il] = u2[f];
        }
    }
}

// ---------------- f32x2 helpers ----------------
typedef unsigned long long ull;
static __device__ __forceinline__ ull pk2(float v) {        // (v, v)
    ull r;
    asm("mov.b64 %0, {%1, %1};" : "=l"(r) : "r"(__float_as_uint(v)));
    return r;
}
static __device__ __forceinline__ ull pkab(float a, float b) {  // (a, b)
    ull r;
    asm("mov.b64 %0, {%1, %2};" : "=l"(r) : "r"(__float_as_uint(a)), "r"(__float_as_uint(b)));
    return r;
}
static __device__ __forceinline__ void fma2(ull& d, ull a, ull b) {
    asm("fma.rn.f32x2 %0, %1, %2, %0;" : "+l"(d) : "l"(a), "l"(b));
}
static __device__ __forceinline__ void unpk2(ull v, float& lo, float& hi) {
    unsigned int a, b;
    asm("mov.b64 {%0, %1}, %2;" : "=r"(a), "=r"(b) : "l"(v));
    lo = __uint_as_float(a);
    hi = __uint_as_float(b);
}
static __device__ __forceinline__ float lo2(ull v) {
    unsigned int a, b;
    asm("mov.b64 {%0, %1}, %2;" : "=r"(a), "=r"(b) : "l"(v));
    return __uint_as_float(a);
}

// ---------------- layout ----------------
// Per channel c the output row base o=(n*128+c)*729 satisfies o mod 4 == c mod 4.
// Phase h(c) = (-c) mod 4: quads cover elements [h, h+4*Kq), head/tail scalar.
// uw smem stores element e of channel c at j*JSTR + (e - h) (head wrapped to end),
// so quad LDS.128 at j*JSTR + 4*q is 16B-aligned.
#define CT 8
#define JSTR 732
#define CHSTR (9 * JSTR)               // 6588
#define UW_F (CT * CHSTR)              // 52704
#define SMEM_BYTES (UW_F * 4 + 960)    // uw + ws2[30][4] (ull)

// ---------------- build helper: k-major coalesced u, f32x2 channel-pair accs ----
// ws2[kg][cp] = (w[c0+2cp], w[c0+2cp+1]) prescaled. Per item: MUL x (1 LDG +
// 1 dup-mov + 4 LDS.64 + 4 fma2), then unpack + 8 STS.32 (shifted layout).
template<int MUL, int IRR, int KOFF, int IBASE>
static __device__ __forceinline__ void build_chunk(const float* __restrict__ ut,
                                                   const ull* __restrict__ ws2,
                                                   float* __restrict__ uw, int tid) {
    constexpr int ITEMS = 729 * IRR;
    for (int idx = tid; idx < ITEMS; idx += 512) {
        ull acc[4] = {0ull, 0ull, 0ull, 0ull};
        #pragma unroll
        for (int k = 0; k < MUL; k++) {
            ull uvd = pk2(__ldg(ut + k * ITEMS + idx));
            #pragma unroll
            for (int cp = 0; cp < 4; cp++)
                fma2(acc[cp], uvd, ws2[(KOFF + k) * 4 + cp]);
        }
        int row = idx / IRR;
        int il  = idx - row * IRR;
        int ab  = row / 9;
        int j   = row - ab * 9;
        int e   = ab * 9 + IBASE + il;
        #pragma unroll
        for (int cp = 0; cp < 4; cp++) {
            float a0, a1;
            unpk2(acc[cp], a0, a1);
            const int ce = 2 * cp, co = 2 * cp + 1;
            const int he = (4 - (ce & 3)) & 3;
            const int ho = (4 - (co & 3)) & 3;
            int pe = (e >= he) ? (e - he) : (729 - he + e);
            int po = (e >= ho) ? (e - ho) : (729 - ho + e);
            uw[ce * CHSTR + j * JSTR + pe] = a0;
            uw[co * CHSTR + j * JSTR + po] = a1;
        }
    }
}

// ---------------- main kernel ----------------
// grid = (C/8, S), 512 threads = 16 warps: warp -> channel (wid>>1), half (wid&1).
// Mainloop = R8 core + software-pipelined x-gather (next group's LDG chain
// issued before current group's tiles).
__global__ __launch_bounds__(512, 1)
void mace_kernel(const float* __restrict__ nf,
                 const float* __restrict__ w0, const float* __restrict__ w1,
                 const float* __restrict__ w2,
                 float* __restrict__ out, int C) {
    extern __shared__ float sm[];
    float* uw = sm;
    ull* ws2 = (ull*)(sm + UW_F);

    const int s = blockIdx.y;
    const int m = g_segCount[s];
    if (m == 0) return;             // CTA-uniform, before any barrier
    const int c0 = blockIdx.x * CT;
    const int segBase = g_segStart[s];
    const int tid = threadIdx.x;

    // ---- stage scaled species weights as channel-pairs: ws2[kg][cp] ----
    if (tid < 120) {
        int kg = tid >> 2, cp = tid & 3;
        const float* wp; int k; float scale; int mul;
        if (kg < 7)       { wp = w0; k = kg;      scale = 0.61478815f; mul = 7;  }
        else if (kg < 18) { wp = w1; k = kg - 7;  scale = 0.54910049f; mul = 11; }
        else              { wp = w2; k = kg - 18; scale = 0.53728497f; mul = 12; }
        const float* base = wp + ((size_t)s * mul + k) * C + c0 + 2 * cp;
        ws2[tid] = pkab(base[0] * scale, base[1] * scale);
    }
    __syncthreads();

    // ---- build uw from k-major u_t (coalesced LDG, f32x2 accumulation) ----
    build_chunk<7, 1, 0, 0>(g_u0t, ws2, uw, tid);
    build_chunk<11, 3, 7, 1>(g_u1t, ws2, uw, tid);
    build_chunk<12, 5, 18, 4>(g_u2t, ws2, uw, tid);
    __syncthreads();

    // ---- main loop (R8 core, pipelined x-gather) ----
    const int lane = tid & 31;
    const int wid  = tid >> 5;          // 0..15
    const int cw   = wid >> 1;          // channel in tile
    const int q    = wid & 1;           // node-group half
    const int crow = c0 + cw;
    const float* uwC = uw + cw * CHSTR;
    const int h  = (4 - (crow & 3)) & 3;  // warp-uniform phase
    const int Kq = (729 - h) >> 2;        // full quads
    const int nL = 729 - 4 * Kq;          // leftover scalars (<=5)

    const int groups = (m + 3) >> 2;
    const int nx0 = lane / 9, jx0 = lane - nx0 * 9;   // gather geometry (fixed)

    // prologue: gather x for first group
    int nidC = 0; float v0C = 0.f, v1C = 0.f;
    if (q < groups) {
        int idx0 = q * 4 + nx0;
        if (idx0 >= m) idx0 = m - 1;
        nidC = g_order[segBase + idx0];
        v0C = nf[((size_t)nidC * C + crow) * 9 + jx0];
        if (lane < 4) {
            int idx1 = q * 4 + 3;
            if (idx1 >= m) idx1 = m - 1;
            v1C = nf[((size_t)g_order[segBase + idx1] * C + crow) * 9 + (5 + lane)];
        }
    }

    for (int g = q; g < groups; g += 2) {
        const int nid = nidC;
        const float v0 = v0C, v1 = v1C;

        // issue next group's gather NOW (consumed next iteration)
        int gn = g + 2;
        if (gn < groups) {
            int idx0 = gn * 4 + nx0;
            if (idx0 >= m) idx0 = m - 1;
            nidC = g_order[segBase + idx0];
            v0C = nf[((size_t)nidC * C + crow) * 9 + jx0];
            if (lane < 4) {
                int idx1 = gn * 4 + 3;
                if (idx1 >= m) idx1 = m - 1;
                v1C = nf[((size_t)g_order[segBase + idx1] * C + crow) * 9 + (5 + lane)];
            }
        }

        unsigned o[4];
        bool valid[4];
        #pragma unroll
        for (int nd = 0; nd < 4; nd++) {
            int n4 = __shfl_sync(0xffffffffu, nid, nd * 9);
            valid[nd] = (g * 4 + nd) < m;
            o[nd] = (unsigned)(n4 * C + crow) * 729u;
        }

        // dup-packed x: xd[nd][j] = (x, x)
        ull xd[4][9];
        #pragma unroll
        for (int nd = 0; nd < 4; nd++) {
            #pragma unroll
            for (int j = 0; j < 9; j++) {
                int el = nd * 9 + j;
                float xv = (el < 32) ? __shfl_sync(0xffffffffu, v0, el)
                                     : __shfl_sync(0xffffffffu, v1, el - 32);
                xd[nd][j] = pk2(xv);
            }
        }

        // body: quads qi = it*32 + lane, elements E = h + 4*qi
        #pragma unroll 1
        for (int it = 0; it < 6; it++) {
            int qi = it * 32 + lane;
            bool act = qi < Kq;
            int qc = act ? qi : 0;
            int soff = 4 * qc;
            ull aA[4] = {0ull, 0ull, 0ull, 0ull};   // (E, E+1)
            ull aB[4] = {0ull, 0ull, 0ull, 0ull};   // (E+2, E+3)
            #pragma unroll
            for (int j = 0; j < 9; j++) {
                ulonglong2 uv = *reinterpret_cast<const ulonglong2*>(uwC + j * JSTR + soff);
                fma2(aA[0], uv.x, xd[0][j]);  fma2(aB[0], uv.y, xd[0][j]);
                fma2(aA[1], uv.x, xd[1][j]);  fma2(aB[1], uv.y, xd[1][j]);
                fma2(aA[2], uv.x, xd[2][j]);  fma2(aB[2], uv.y, xd[2][j]);
                fma2(aA[3], uv.x, xd[3][j]);  fma2(aB[3], uv.y, xd[3][j]);
            }
            int E = h + 4 * qc;
            #pragma unroll
            for (int nd = 0; nd < 4; nd++) {
                float4 f4;
                unpk2(aA[nd], f4.x, f4.y);
                unpk2(aB[nd], f4.z, f4.w);
                if (act && valid[nd])
                    __stcs(reinterpret_cast<float4*>(out + o[nd] + E), f4);
            }
        }

        // leftovers: head elements [0,h) and tail [h+4Kq, 729): nL lanes
        if (lane < nL) {
            int e   = (lane < h) ? lane : (4 * Kq + lane);
            int pos = (lane < h) ? (729 - h + lane) : (4 * Kq + lane - h);
            float b0 = 0.f, b1 = 0.f, b2 = 0.f, b3 = 0.f;
            #pragma unroll
            for (int j = 0; j < 9; j++) {
                float uvv = uwC[j * JSTR + pos];
                b0 += uvv * lo2(xd[0][j]);
                b1 += uvv * lo2(xd[1][j]);
                b2 += uvv * lo2(xd[2][j]);
                b3 += uvv * lo2(xd[3][j]);
            }
            if (valid[0]) __stcs(out + o[0] + e, b0);
            if (valid[1]) __stcs(out + o[1] + e, b1);
            if (valid[2]) __stcs(out + o[2] + e, b2);
            if (valid[3]) __stcs(out + o[3] + e, b3);
        }
    }
}

// ---------------- launch ----------------
extern "C" void kernel_launch(void* const* d_in, const int* in_sizes, int n_in,
                              void* d_out, int out_size) {
    const float *nf = nullptr, *u0 = nullptr, *u1 = nullptr, *u2 = nullptr;
    const float *w0 = nullptr, *w1 = nullptr, *w2 = nullptr;
    const int* index = nullptr;
    int N = 0, nf_sz = 0, w0_sz = 0;
    for (int i = 0; i < n_in; i++) {
        int sz = in_sizes[i];
        switch (sz) {
            case 5103:    u0 = (const float*)d_in[i]; break;
            case 24057:   u1 = (const float*)d_in[i]; break;
            case 43740:   u2 = (const float*)d_in[i]; break;
            case 44800:   w0 = (const float*)d_in[i]; w0_sz = sz; break;
            case 70400:   w1 = (const float*)d_in[i]; break;
            case 76800:   w2 = (const float*)d_in[i]; break;
            case 2048:    index = (const int*)d_in[i]; N = sz; break;
            case 2359296: nf = (const float*)d_in[i]; nf_sz = sz; break;
            default: break;
        }
    }
    if (!nf || !index || !u0 || !u1 || !u2 || !w0 || !w1 || !w2) return;

    const int C = nf_sz / (N * 9);        // 128
    const int S = w0_sz / (7 * C);        // 50

    setup_kernel<<<17, 1024>>>(index, N, u0, u1, u2);

    cudaFuncSetAttribute(mace_kernel,
                         cudaFuncAttributeMaxDynamicSharedMemorySize, SMEM_BYTES);
    dim3 grid(C / CT, S);
    mace_kernel<<<grid, 512, SMEM_BYTES>>>(nf, w0, w1, w2, (float*)d_out, C);
}